// round 8
// baseline (speedup 1.0000x reference)
#include <cuda_runtime.h>
#include <cuda_fp16.h>
#include <cstdint>

#define Bc 32
#define Tc 128
#define Ec 512
#define Hc 1024
#define Vc 32000
#define NTOK (Bc*Tc)      // 4096 tokens
#define G4H (4*Hc)        // 4096 gate rows

// ---------------- device scratch (no runtime alloc allowed) ----------------
__device__ float g_xg[(size_t)NTOK * G4H];                    // 64 MB
// padded h history: rows [0,32) = h_{-1} = 0; row (t+1)*32+b = h_t[b]
__device__ __align__(16) __half g_hsh_pad[(size_t)(NTOK + Bc) * Hc];
__device__ __align__(16) __half g_wh[(size_t)Vc * Hc];        // fc_w fp16 (64 MB)
__device__ unsigned int g_sync;

// ---------------- small helpers ----------------
static __device__ __forceinline__ uint32_t saddr(const void* p){
    return (uint32_t)__cvta_generic_to_shared(p);
}
static __device__ __forceinline__ void ldm_x4(uint32_t* r, uint32_t a){
    asm volatile("ldmatrix.sync.aligned.m8n8.x4.shared.b16 {%0,%1,%2,%3},[%4];"
        : "=r"(r[0]),"=r"(r[1]),"=r"(r[2]),"=r"(r[3]) : "r"(a));
}
static __device__ __forceinline__ void ldm_x2(uint32_t* r, uint32_t a){
    asm volatile("ldmatrix.sync.aligned.m8n8.x2.shared.b16 {%0,%1},[%2];"
        : "=r"(r[0]),"=r"(r[1]) : "r"(a));
}
static __device__ __forceinline__ void mma_f16(float* d, const uint32_t* a, const uint32_t* b){
    asm volatile("mma.sync.aligned.m16n8k16.row.col.f32.f16.f16.f32 "
        "{%0,%1,%2,%3},{%4,%5,%6,%7},{%8,%9},{%0,%1,%2,%3};"
        : "+f"(d[0]),"+f"(d[1]),"+f"(d[2]),"+f"(d[3])
        : "r"(a[0]),"r"(a[1]),"r"(a[2]),"r"(a[3]),"r"(b[0]),"r"(b[1]));
}
static __device__ __forceinline__ float sigmoidf_(float x){
    return 1.0f/(1.0f + __expf(-x));
}
static __device__ __forceinline__ void cp16(uint32_t dst, const void* src){
    asm volatile("cp.async.cg.shared.global [%0],[%1],16;\n" :: "r"(dst), "l"(src));
}

// ---------------- init: zero h_{-1} rows and sync counter (every replay) ---
__global__ void init_kernel(){
    int tid = blockIdx.x*blockDim.x + threadIdx.x;
    uint4* p = (uint4*)g_hsh_pad;               // first 32*Hc halves = 4096 uint4
    if (tid < 4096) p[tid] = make_uint4(0,0,0,0);
    if (tid == 0) g_sync = 0u;
}

// ---------------- prep: fc_w (f32) -> g_wh (fp16) ----------------
__global__ void __launch_bounds__(256) wh_prep_kernel(const float* __restrict__ fc_w){
    size_t total8 = (size_t)Vc * Hc / 8;
    size_t stride = (size_t)gridDim.x * blockDim.x;
    for (size_t g = blockIdx.x*(size_t)blockDim.x + threadIdx.x; g < total8; g += stride) {
        float4 v0 = *(const float4*)(fc_w + g*8);
        float4 v1 = *(const float4*)(fc_w + g*8 + 4);
        __half2 h0 = __float22half2_rn(make_float2(v0.x, v0.y));
        __half2 h1 = __float22half2_rn(make_float2(v0.z, v0.w));
        __half2 h2 = __float22half2_rn(make_float2(v1.x, v1.y));
        __half2 h3 = __float22half2_rn(make_float2(v1.z, v1.w));
        uint4 o;
        o.x = *(uint32_t*)&h0; o.y = *(uint32_t*)&h1;
        o.z = *(uint32_t*)&h2; o.w = *(uint32_t*)&h3;
        *(uint4*)(g_wh + g*8) = o;
    }
}

// ---------------- kernel A: xg = embed[x] @ W_ih^T + b_ih + b_hh (fp16) ----
#define A_BK 64
#define A_LD (A_BK + 8)

__global__ void __launch_bounds__(256) xg_kernel(
    const int* __restrict__ x, const float* __restrict__ embed,
    const float* __restrict__ W_ih, const float* __restrict__ b_ih,
    const float* __restrict__ b_hh)
{
    __shared__ __half sA[128 * A_LD];
    __shared__ __half sB[128 * A_LD];
    const int tid = threadIdx.x, lane = tid & 31, w = tid >> 5;
    const int bm = blockIdx.x, bn = blockIdx.y;
    const int wm = (w >> 2) * 64, wn = (w & 3) * 32;

    float acc[4][4][4];
#pragma unroll
    for (int i=0;i<4;i++)
#pragma unroll
        for (int j=0;j<4;j++)
#pragma unroll
            for (int k=0;k<4;k++) acc[i][j][k]=0.f;

    for (int kt = 0; kt < Ec / A_BK; ++kt) {
        const int k0 = kt * A_BK;
#pragma unroll
        for (int i = 0; i < 8; ++i) {
            int idx = tid + i*256;
            int r = idx >> 4, c4 = idx & 15;
            int m = bm*128 + r;
            int b = m & 31, t = m >> 5;
            int vid = x[b*Tc + t];
            float4 v = *(const float4*)(embed + (size_t)vid*Ec + k0 + c4*4);
            __half2* d = (__half2*)(sA + r*A_LD + c4*4);
            d[0] = __float22half2_rn(make_float2(v.x, v.y));
            d[1] = __float22half2_rn(make_float2(v.z, v.w));
        }
#pragma unroll
        for (int i = 0; i < 8; ++i) {
            int idx = tid + i*256;
            int r = idx >> 4, c4 = idx & 15;
            int n = bn*128 + r;
            float4 v = *(const float4*)(W_ih + (size_t)n*Ec + k0 + c4*4);
            __half2* d = (__half2*)(sB + r*A_LD + c4*4);
            d[0] = __float22half2_rn(make_float2(v.x, v.y));
            d[1] = __float22half2_rn(make_float2(v.z, v.w));
        }
        __syncthreads();
#pragma unroll
        for (int ks = 0; ks < A_BK; ks += 16) {
            uint32_t af[4][4], bf[4][2];
#pragma unroll
            for (int mt = 0; mt < 4; ++mt) {
                int row = wm + mt*16 + (lane & 7) + ((lane >> 3) & 1) * 8;
                int col = ks + (lane >> 4) * 8;
                ldm_x4(af[mt], saddr(sA + row*A_LD + col));
            }
#pragma unroll
            for (int nt = 0; nt < 4; ++nt) {
                int l = lane & 15;
                int row = wn + nt*8 + (l & 7);
                int col = ks + ((l >> 3) & 1) * 8;
                ldm_x2(bf[nt], saddr(sB + row*A_LD + col));
            }
#pragma unroll
            for (int mt = 0; mt < 4; ++mt)
#pragma unroll
                for (int nt = 0; nt < 4; ++nt)
                    mma_f16(acc[mt][nt], af[mt], bf[nt]);
        }
        __syncthreads();
    }
#pragma unroll
    for (int nt = 0; nt < 4; ++nt) {
        int col = bn*128 + wn + nt*8 + (lane & 3)*2;
        float bia0 = b_ih[col]   + b_hh[col];
        float bia1 = b_ih[col+1] + b_hh[col+1];
#pragma unroll
        for (int mt = 0; mt < 4; ++mt) {
            int row = bm*128 + wm + mt*16 + (lane >> 2);
            *(float2*)(g_xg + (size_t)row*G4H + col) =
                make_float2(acc[mt][nt][0]+bia0, acc[mt][nt][1]+bia1);
            *(float2*)(g_xg + (size_t)(row+8)*G4H + col) =
                make_float2(acc[mt][nt][2]+bia0, acc[mt][nt][3]+bia1);
        }
    }
}

// ---------------- recurrence: 128 CTAs x 256 thr (round-7 proven) ----------
#define L_LDH 1032                       // half row stride (2064 B)
#define L_SPW (32*34)                    // floats per warp partial tile
#define LSTM_SMEM (32*L_LDH*2 /*sW*/ + 32*L_LDH*2 /*sH*/ + 8*L_SPW*4 /*sP*/)

__global__ void __launch_bounds__(256, 1) lstm_kernel(const float* __restrict__ W_hh)
{
    extern __shared__ unsigned char smem[];
    __half* sW = (__half*)smem;                       // 32 x L_LDH (init only)
    __half* sH = sW + 32*L_LDH;                       // 32 x L_LDH
    float* sP = (float*)(sH + 32*L_LDH);              // 8 warps x 32 x 34
    const int tid = threadIdx.x, lane = tid & 31, w = tid >> 5;
    const int n = blockIdx.x;                // 0..127
    const int ub = tid & 7, bb = tid >> 3;   // this thread's (u, b) pair

    // one-time: W_hh slice (32 gate rows x 1024) fp32->fp16 into smem
    for (int idx = tid; idx < 32*256; idx += 256) {
        int r = idx >> 8, c4 = idx & 255;
        int gr = (r >> 3)*Hc + n*8 + (r & 7);
        float4 v = *(const float4*)(W_hh + (size_t)gr*Hc + c4*4);
        __half2* d = (__half2*)(sW + r*L_LDH + c4*4);
        d[0] = __float22half2_rn(make_float2(v.x, v.y));
        d[1] = __float22half2_rn(make_float2(v.z, v.w));
    }
    __syncthreads();

    // hoist W fragments into registers (reused for all 128 steps)
    uint32_t bw[8][4][2];
#pragma unroll
    for (int kt = 0; kt < 8; ++kt) {
        const int ks = w*128 + kt*16;
#pragma unroll
        for (int nt = 0; nt < 4; ++nt) {
            int l = lane & 15;
            int row = nt*8 + (l & 7);
            int col = ks + ((l >> 3) & 1) * 8;
            ldm_x2(bw[kt][nt], saddr(sW + row*L_LDH + col));
        }
    }
    float creg = 0.f;
    __syncthreads();

    for (int t = 0; t < Tc; ++t) {
        // prefetch xg for this thread's (b,u) — independent of h
        const float* xgp = g_xg + (size_t)(t*32 + bb)*G4H + n*8 + ub;
        float x0 = __ldcg(xgp);
        float x1 = __ldcg(xgp + Hc);
        float x2 = __ldcg(xgp + 2*Hc);
        float x3 = __ldcg(xgp + 3*Hc);

        // warp-private h slice load: warp w needs cols [128w, 128w+128) only
        {
            const __half* hsrc = g_hsh_pad + (size_t)(t*32)*Hc + w*128;
#pragma unroll
            for (int i = 0; i < 16; ++i) {
                int idx = i*32 + lane;          // 0..511
                int r = idx >> 4, cw = idx & 15;
                const uint4* gp = (const uint4*)(hsrc + (size_t)r*Hc + cw*8);
                uint4 v = __ldcg(gp);
                *(uint4*)(sH + r*L_LDH + w*128 + cw*8) = v;
            }
        }
        __syncwarp();

        // mma over this warp's K slice (A from smem via ldmatrix, W from regs)
        float acc[2][4][4];
#pragma unroll
        for (int i=0;i<2;i++)
#pragma unroll
            for (int j=0;j<4;j++)
#pragma unroll
                for (int k=0;k<4;k++) acc[i][j][k]=0.f;

#pragma unroll
        for (int kt = 0; kt < 8; ++kt) {
            const int ks = w*128 + kt*16;
            uint32_t af[2][4];
#pragma unroll
            for (int mt = 0; mt < 2; ++mt) {
                int row = mt*16 + (lane & 7) + ((lane >> 3) & 1) * 8;
                int col = ks + (lane >> 4) * 8;
                ldm_x4(af[mt], saddr(sH + row*L_LDH + col));
            }
#pragma unroll
            for (int mt = 0; mt < 2; ++mt)
#pragma unroll
                for (int nt = 0; nt < 4; ++nt)
                    mma_f16(acc[mt][nt], af[mt], bw[kt][nt]);
        }
        // dump partials: sP[w][row][col], stride 34
        float* sPw = sP + w*L_SPW;
#pragma unroll
        for (int mt = 0; mt < 2; ++mt)
#pragma unroll
            for (int nt = 0; nt < 4; ++nt) {
                int row = mt*16 + (lane >> 2);
                int col = nt*8 + (lane & 3)*2;
                *(float2*)(sPw + row*34 + col)     = make_float2(acc[mt][nt][0], acc[mt][nt][1]);
                *(float2*)(sPw + (row+8)*34 + col) = make_float2(acc[mt][nt][2], acc[mt][nt][3]);
            }
        __syncthreads();

        // reduce 8 partials + gate update; thread owns (bb, ub)
        float g0=0.f, g1=0.f, g2=0.f, g3=0.f;
#pragma unroll
        for (int ww = 0; ww < 8; ++ww) {
            const float* p = sP + ww*L_SPW + bb*34 + ub;
            g0 += p[0]; g1 += p[8]; g2 += p[16]; g3 += p[24];
        }
        float gi = sigmoidf_(g0 + x0);
        float gf = sigmoidf_(g1 + x1);
        float gg = tanhf   (g2 + x2);
        float go = sigmoidf_(g3 + x3);
        creg = gf * creg + gi * gg;
        float h = go * tanhf(creg);
        g_hsh_pad[(size_t)((t+1)*32 + bb)*Hc + n*8 + ub] = __float2half_rn(h);

        // 1-hop grid barrier: release-add + acquire poll on the counter
        __syncthreads();
        if (tid == 0) {
            asm volatile("red.release.gpu.global.add.u32 [%0], %1;"
                         :: "l"(&g_sync), "r"(1u) : "memory");
            unsigned f;
            const unsigned target = 128u*(unsigned)(t+1);
            do {
                asm volatile("ld.acquire.gpu.global.u32 %0, [%1];"
                             : "=r"(f) : "l"(&g_sync) : "memory");
            } while (f < target);
        }
        __syncthreads();
    }
}

// ---------------- FC: out = hs @ fc_w^T + fc_b --------------------------------
// CTA tile 128(M) x 256(N), 8 warps in 2x4, warp tile 64x64. 3-stage cp.async.
#define F_LD 72                        // halves per smem row (144 B)
#define F_ATILE (128 * F_LD)           // A tile halves
#define F_BTILE (256 * F_LD)           // B tile halves
#define F_STAGE (F_ATILE + F_BTILE)
#define FC_NS 3
#define FC_SMEM (FC_NS * F_STAGE * 2)  // 165888 B

__global__ void __launch_bounds__(256, 1) fc_kernel(
    const float* __restrict__ fc_b, float* __restrict__ out)
{
    extern __shared__ __half fsm[];
    const int tid = threadIdx.x, lane = tid & 31, w = tid >> 5;
    const int bm = blockIdx.x, bn = blockIdx.y;
    const int wm = (w >> 2) * 64, wn = (w & 3) * 64;

    const __half* Abase = g_hsh_pad + (size_t)Bc*Hc + (size_t)(bm*128)*Hc;
    const __half* Bbase = g_wh + (size_t)(bn*256)*Hc;

    float acc[4][8][4];
#pragma unroll
    for (int i=0;i<4;i++)
#pragma unroll
        for (int j=0;j<8;j++)
#pragma unroll
            for (int k=0;k<4;k++) acc[i][j][k]=0.f;

    auto load_stage = [&](int kt, int buf){
        __half* sA = fsm + buf * F_STAGE;
        __half* sB = sA + F_ATILE;
        const int k0 = kt * 64;
#pragma unroll
        for (int i = 0; i < 4; ++i) {      // A: 1024 granules
            int g = tid + i*256; int r = g >> 3, c = g & 7;
            cp16(saddr(sA + r*F_LD + c*8), Abase + (size_t)r*Hc + k0 + c*8);
        }
#pragma unroll
        for (int i = 0; i < 8; ++i) {      // B: 2048 granules
            int g = tid + i*256; int r = g >> 3, c = g & 7;
            cp16(saddr(sB + r*F_LD + c*8), Bbase + (size_t)r*Hc + k0 + c*8);
        }
        asm volatile("cp.async.commit_group;" ::: "memory");
    };

    load_stage(0, 0);
    load_stage(1, 1);

    for (int kt = 0; kt < 16; ++kt) {
        if (kt < 15) asm volatile("cp.async.wait_group 1;" ::: "memory");
        else         asm volatile("cp.async.wait_group 0;" ::: "memory");
        __syncthreads();
        if (kt + 2 < 16) load_stage(kt + 2, (kt + 2) % FC_NS);

        const __half* sA = fsm + (kt % FC_NS) * F_STAGE;
        const __half* sB = sA + F_ATILE;
#pragma unroll
        for (int ks = 0; ks < 64; ks += 16) {
            uint32_t af[4][4], bf[8][2];
#pragma unroll
            for (int mt = 0; mt < 4; ++mt) {
                int row = wm + mt*16 + (lane & 7) + ((lane >> 3) & 1) * 8;
                int col = ks + (lane >> 4) * 8;
                ldm_x4(af[mt], saddr(sA + row*F_LD + col));
            }
#pragma unroll
            for (int nt = 0; nt < 8; ++nt) {
                int l = lane & 15;
                int row = wn + nt*8 + (l & 7);
                int col = ks + ((l >> 3) & 1) * 8;
                ldm_x2(bf[nt], saddr(sB + row*F_LD + col));
            }
#pragma unroll
            for (int mt = 0; mt < 4; ++mt)
#pragma unroll
                for (int nt = 0; nt < 8; ++nt)
                    mma_f16(acc[mt][nt], af[mt], bf[nt]);
        }
    }

    // epilogue: + fc_b, scatter m=t*32+b -> out[(b*T+t)*V + v]
#pragma unroll
    for (int nt = 0; nt < 8; ++nt) {
        int v = bn*256 + wn + nt*8 + (lane & 3)*2;
        float bia0 = fc_b[v], bia1 = fc_b[v+1];
#pragma unroll
        for (int mt = 0; mt < 4; ++mt) {
            int m = bm*128 + wm + mt*16 + (lane >> 2);
            int b0 = m & 31, t0 = m >> 5;
            *(float2*)(out + (size_t)(b0*Tc + t0)*Vc + v) =
                make_float2(acc[mt][nt][0]+bia0, acc[mt][nt][1]+bia1);
            int m2 = m + 8;
            int b1 = m2 & 31, t1 = m2 >> 5;
            *(float2*)(out + (size_t)(b1*Tc + t1)*Vc + v) =
                make_float2(acc[mt][nt][2]+bia0, acc[mt][nt][3]+bia1);
        }
    }
}

// ---------------- launch ----------------------------------------------------
extern "C" void kernel_launch(void* const* d_in, const int* in_sizes, int n_in,
                              void* d_out, int out_size)
{
    const int*   x     = (const int*)  d_in[0];
    const float* embed = (const float*)d_in[1];
    const float* W_ih  = (const float*)d_in[2];
    const float* W_hh  = (const float*)d_in[3];
    const float* b_ih  = (const float*)d_in[4];
    const float* b_hh  = (const float*)d_in[5];
    const float* fc_w  = (const float*)d_in[6];
    const float* fc_b  = (const float*)d_in[7];
    float* out = (float*)d_out;

    cudaFuncSetAttribute(lstm_kernel, cudaFuncAttributeMaxDynamicSharedMemorySize, LSTM_SMEM);
    cudaFuncSetAttribute(fc_kernel,   cudaFuncAttributeMaxDynamicSharedMemorySize, FC_SMEM);

    init_kernel<<<32, 256>>>();
    wh_prep_kernel<<<2048, 256>>>(fc_w);
    xg_kernel<<<dim3(32, 32), 256>>>(x, embed, W_ih, b_ih, b_hh);
    lstm_kernel<<<128, 256, LSTM_SMEM>>>(W_hh);
    fc_kernel<<<dim3(32, 125), 256, FC_SMEM>>>(fc_b, out);
}

// round 9
// speedup vs baseline: 1.0310x; 1.0310x over previous
#include <cuda_runtime.h>
#include <cuda_fp16.h>
#include <cstdint>

#define Bc 32
#define Tc 128
#define Ec 512
#define Hc 1024
#define Vc 32000
#define NTOK (Bc*Tc)      // 4096 tokens
#define G4H (4*Hc)        // 4096 gate rows

// ---------------- device scratch (no runtime alloc allowed) ----------------
__device__ float g_xg[(size_t)NTOK * G4H];                    // 64 MB
// padded h history: rows [0,32) = h_{-1} = 0; row (t+1)*32+b = h_t[b]
__device__ __align__(16) __half g_hsh_pad[(size_t)(NTOK + Bc) * Hc];
__device__ __align__(16) __half g_wh[(size_t)Vc * Hc];        // fc_w fp16 (64 MB)
__device__ __align__(128) unsigned int g_syncg[8][32];        // per-K-slice counters

// ---------------- small helpers ----------------
static __device__ __forceinline__ uint32_t saddr(const void* p){
    return (uint32_t)__cvta_generic_to_shared(p);
}
static __device__ __forceinline__ void ldm_x4(uint32_t* r, uint32_t a){
    asm volatile("ldmatrix.sync.aligned.m8n8.x4.shared.b16 {%0,%1,%2,%3},[%4];"
        : "=r"(r[0]),"=r"(r[1]),"=r"(r[2]),"=r"(r[3]) : "r"(a));
}
static __device__ __forceinline__ void ldm_x2(uint32_t* r, uint32_t a){
    asm volatile("ldmatrix.sync.aligned.m8n8.x2.shared.b16 {%0,%1},[%2];"
        : "=r"(r[0]),"=r"(r[1]) : "r"(a));
}
static __device__ __forceinline__ void mma_f16(float* d, const uint32_t* a, const uint32_t* b){
    asm volatile("mma.sync.aligned.m16n8k16.row.col.f32.f16.f16.f32 "
        "{%0,%1,%2,%3},{%4,%5,%6,%7},{%8,%9},{%0,%1,%2,%3};"
        : "+f"(d[0]),"+f"(d[1]),"+f"(d[2]),"+f"(d[3])
        : "r"(a[0]),"r"(a[1]),"r"(a[2]),"r"(a[3]),"r"(b[0]),"r"(b[1]));
}
static __device__ __forceinline__ float sigmoidf_(float x){
    return 1.0f/(1.0f + __expf(-x));
}
static __device__ __forceinline__ void cp16(uint32_t dst, const void* src){
    asm volatile("cp.async.cg.shared.global [%0],[%1],16;\n" :: "r"(dst), "l"(src));
}

// ---------------- init: zero h_{-1} rows and group counters (every replay) --
__global__ void init_kernel(){
    int tid = blockIdx.x*blockDim.x + threadIdx.x;
    uint4* p = (uint4*)g_hsh_pad;               // first 32*Hc halves = 4096 uint4
    if (tid < 4096) p[tid] = make_uint4(0,0,0,0);
    if (tid < 8) g_syncg[tid][0] = 0u;
}

// ---------------- prep: fc_w (f32) -> g_wh (fp16) ----------------
__global__ void __launch_bounds__(256) wh_prep_kernel(const float* __restrict__ fc_w){
    size_t total8 = (size_t)Vc * Hc / 8;
    size_t stride = (size_t)gridDim.x * blockDim.x;
    for (size_t g = blockIdx.x*(size_t)blockDim.x + threadIdx.x; g < total8; g += stride) {
        float4 v0 = *(const float4*)(fc_w + g*8);
        float4 v1 = *(const float4*)(fc_w + g*8 + 4);
        __half2 h0 = __float22half2_rn(make_float2(v0.x, v0.y));
        __half2 h1 = __float22half2_rn(make_float2(v0.z, v0.w));
        __half2 h2 = __float22half2_rn(make_float2(v1.x, v1.y));
        __half2 h3 = __float22half2_rn(make_float2(v1.z, v1.w));
        uint4 o;
        o.x = *(uint32_t*)&h0; o.y = *(uint32_t*)&h1;
        o.z = *(uint32_t*)&h2; o.w = *(uint32_t*)&h3;
        *(uint4*)(g_wh + g*8) = o;
    }
}

// ---------------- kernel A: xg = embed[x] @ W_ih^T + b_ih + b_hh (fp16) ----
#define A_BK 64
#define A_LD (A_BK + 8)

__global__ void __launch_bounds__(256) xg_kernel(
    const int* __restrict__ x, const float* __restrict__ embed,
    const float* __restrict__ W_ih, const float* __restrict__ b_ih,
    const float* __restrict__ b_hh)
{
    __shared__ __half sA[128 * A_LD];
    __shared__ __half sB[128 * A_LD];
    const int tid = threadIdx.x, lane = tid & 31, w = tid >> 5;
    const int bm = blockIdx.x, bn = blockIdx.y;
    const int wm = (w >> 2) * 64, wn = (w & 3) * 32;

    float acc[4][4][4];
#pragma unroll
    for (int i=0;i<4;i++)
#pragma unroll
        for (int j=0;j<4;j++)
#pragma unroll
            for (int k=0;k<4;k++) acc[i][j][k]=0.f;

    for (int kt = 0; kt < Ec / A_BK; ++kt) {
        const int k0 = kt * A_BK;
#pragma unroll
        for (int i = 0; i < 8; ++i) {
            int idx = tid + i*256;
            int r = idx >> 4, c4 = idx & 15;
            int m = bm*128 + r;
            int b = m & 31, t = m >> 5;
            int vid = x[b*Tc + t];
            float4 v = *(const float4*)(embed + (size_t)vid*Ec + k0 + c4*4);
            __half2* d = (__half2*)(sA + r*A_LD + c4*4);
            d[0] = __float22half2_rn(make_float2(v.x, v.y));
            d[1] = __float22half2_rn(make_float2(v.z, v.w));
        }
#pragma unroll
        for (int i = 0; i < 8; ++i) {
            int idx = tid + i*256;
            int r = idx >> 4, c4 = idx & 15;
            int n = bn*128 + r;
            float4 v = *(const float4*)(W_ih + (size_t)n*Ec + k0 + c4*4);
            __half2* d = (__half2*)(sB + r*A_LD + c4*4);
            d[0] = __float22half2_rn(make_float2(v.x, v.y));
            d[1] = __float22half2_rn(make_float2(v.z, v.w));
        }
        __syncthreads();
#pragma unroll
        for (int ks = 0; ks < A_BK; ks += 16) {
            uint32_t af[4][4], bf[4][2];
#pragma unroll
            for (int mt = 0; mt < 4; ++mt) {
                int row = wm + mt*16 + (lane & 7) + ((lane >> 3) & 1) * 8;
                int col = ks + (lane >> 4) * 8;
                ldm_x4(af[mt], saddr(sA + row*A_LD + col));
            }
#pragma unroll
            for (int nt = 0; nt < 4; ++nt) {
                int l = lane & 15;
                int row = wn + nt*8 + (l & 7);
                int col = ks + ((l >> 3) & 1) * 8;
                ldm_x2(bf[nt], saddr(sB + row*A_LD + col));
            }
#pragma unroll
            for (int mt = 0; mt < 4; ++mt)
#pragma unroll
                for (int nt = 0; nt < 4; ++nt)
                    mma_f16(acc[mt][nt], af[mt], bf[nt]);
        }
        __syncthreads();
    }
#pragma unroll
    for (int nt = 0; nt < 4; ++nt) {
        int col = bn*128 + wn + nt*8 + (lane & 3)*2;
        float bia0 = b_ih[col]   + b_hh[col];
        float bia1 = b_ih[col+1] + b_hh[col+1];
#pragma unroll
        for (int mt = 0; mt < 4; ++mt) {
            int row = bm*128 + wm + mt*16 + (lane >> 2);
            *(float2*)(g_xg + (size_t)row*G4H + col) =
                make_float2(acc[mt][nt][0]+bia0, acc[mt][nt][1]+bia1);
            *(float2*)(g_xg + (size_t)(row+8)*G4H + col) =
                make_float2(acc[mt][nt][2]+bia0, acc[mt][nt][3]+bia1);
        }
    }
}

// ---------------- recurrence: 128 CTAs x 256 thr, per-slice group flags -----
// CTA n owns hidden units [8n, 8n+8) -> 32 gate rows. Warp w handles K slice
// [128w, 128w+128), produced by CTA group w = [16w, 16w+16). Warp w waits only
// on its group's counter, so early slices pipeline into late producers.
#define L_LDH 1032                       // half row stride (2064 B)
#define L_SPW (32*34)                    // floats per warp partial tile
#define LSTM_SMEM (32*L_LDH*2 /*sW*/ + 32*L_LDH*2 /*sH*/ + 8*L_SPW*4 /*sP*/ + 256*2 /*sHo*/)

__global__ void __launch_bounds__(256, 1) lstm_kernel(const float* __restrict__ W_hh)
{
    extern __shared__ unsigned char smem[];
    __half* sW = (__half*)smem;                       // 32 x L_LDH (init only)
    __half* sH = sW + 32*L_LDH;                       // 32 x L_LDH
    float* sP = (float*)(sH + 32*L_LDH);              // 8 warps x 32 x 34
    __half* sHo = (__half*)(sP + 8*L_SPW);            // 32 x 8 output h
    const int tid = threadIdx.x, lane = tid & 31, w = tid >> 5;
    const int n = blockIdx.x;                // 0..127
    const int grp = n >> 4;                  // this CTA's producer group
    const int ub = tid & 7, bb = tid >> 3;   // this thread's (u, b) pair

    // one-time: W_hh slice (32 gate rows x 1024) fp32->fp16 into smem
    for (int idx = tid; idx < 32*256; idx += 256) {
        int r = idx >> 8, c4 = idx & 255;
        int gr = (r >> 3)*Hc + n*8 + (r & 7);
        float4 v = *(const float4*)(W_hh + (size_t)gr*Hc + c4*4);
        __half2* d = (__half2*)(sW + r*L_LDH + c4*4);
        d[0] = __float22half2_rn(make_float2(v.x, v.y));
        d[1] = __float22half2_rn(make_float2(v.z, v.w));
    }
    __syncthreads();

    // hoist W fragments into registers (reused for all 128 steps)
    uint32_t bw[8][4][2];
#pragma unroll
    for (int kt = 0; kt < 8; ++kt) {
        const int ks = w*128 + kt*16;
#pragma unroll
        for (int nt = 0; nt < 4; ++nt) {
            int l = lane & 15;
            int row = nt*8 + (l & 7);
            int col = ks + ((l >> 3) & 1) * 8;
            ldm_x2(bw[kt][nt], saddr(sW + row*L_LDH + col));
        }
    }
    float creg = 0.f;
    __syncthreads();

    for (int t = 0; t < Tc; ++t) {
        // prefetch xg for this thread's (b,u) — independent of h
        const float* xgp = g_xg + (size_t)(t*32 + bb)*G4H + n*8 + ub;
        float x0 = __ldcg(xgp);
        float x1 = __ldcg(xgp + Hc);
        float x2 = __ldcg(xgp + 2*Hc);
        float x3 = __ldcg(xgp + 3*Hc);

        // per-warp wait: slice w's producers (group w) must have finished step t-1
        if (lane == 0 && t > 0) {
            const unsigned target = 16u*(unsigned)t;
            unsigned f;
            do {
                asm volatile("ld.acquire.gpu.global.u32 %0, [%1];"
                             : "=r"(f) : "l"(&g_syncg[w][0]) : "memory");
            } while (f < target);
        }
        __syncwarp();

        // warp-private h slice load: warp w needs cols [128w, 128w+128) only
        {
            const __half* hsrc = g_hsh_pad + (size_t)(t*32)*Hc + w*128;
#pragma unroll
            for (int i = 0; i < 16; ++i) {
                int idx = i*32 + lane;          // 0..511
                int r = idx >> 4, cw = idx & 15;
                const uint4* gp = (const uint4*)(hsrc + (size_t)r*Hc + cw*8);
                uint4 v = __ldcg(gp);
                *(uint4*)(sH + r*L_LDH + w*128 + cw*8) = v;
            }
        }
        __syncwarp();

        // mma over this warp's K slice (A from smem via ldmatrix, W from regs)
        float acc[2][4][4];
#pragma unroll
        for (int i=0;i<2;i++)
#pragma unroll
            for (int j=0;j<4;j++)
#pragma unroll
                for (int k=0;k<4;k++) acc[i][j][k]=0.f;

#pragma unroll
        for (int kt = 0; kt < 8; ++kt) {
            const int ks = w*128 + kt*16;
            uint32_t af[2][4];
#pragma unroll
            for (int mt = 0; mt < 2; ++mt) {
                int row = mt*16 + (lane & 7) + ((lane >> 3) & 1) * 8;
                int col = ks + (lane >> 4) * 8;
                ldm_x4(af[mt], saddr(sH + row*L_LDH + col));
            }
#pragma unroll
            for (int mt = 0; mt < 2; ++mt)
#pragma unroll
                for (int nt = 0; nt < 4; ++nt)
                    mma_f16(acc[mt][nt], af[mt], bw[kt][nt]);
        }
        // dump partials: sP[w][row][col], stride 34
        float* sPw = sP + w*L_SPW;
#pragma unroll
        for (int mt = 0; mt < 2; ++mt)
#pragma unroll
            for (int nt = 0; nt < 4; ++nt) {
                int row = mt*16 + (lane >> 2);
                int col = nt*8 + (lane & 3)*2;
                *(float2*)(sPw + row*34 + col)     = make_float2(acc[mt][nt][0], acc[mt][nt][1]);
                *(float2*)(sPw + (row+8)*34 + col) = make_float2(acc[mt][nt][2], acc[mt][nt][3]);
            }
        __syncthreads();

        // reduce 8 partials + gate update; thread owns (bb, ub)
        float g0=0.f, g1=0.f, g2=0.f, g3=0.f;
#pragma unroll
        for (int ww = 0; ww < 8; ++ww) {
            const float* p = sP + ww*L_SPW + bb*34 + ub;
            g0 += p[0]; g1 += p[8]; g2 += p[16]; g3 += p[24];
        }
        float gi = sigmoidf_(g0 + x0);
        float gf = sigmoidf_(g1 + x1);
        float gg = tanhf   (g2 + x2);
        float go = sigmoidf_(g3 + x3);
        creg = gf * creg + gi * gg;
        float h = go * tanhf(creg);
        sHo[bb*8 + ub] = __float2half_rn(h);
        __syncthreads();

        // warp 0: coalesced h store (32 rows x 16 B) then release group counter
        if (w == 0) {
            uint4 v = *(uint4*)(sHo + lane*8);
            *(uint4*)(g_hsh_pad + (size_t)((t+1)*32 + lane)*Hc + n*8) = v;
            __syncwarp();
            if (lane == 0)
                asm volatile("red.release.gpu.global.add.u32 [%0], %1;"
                             :: "l"(&g_syncg[grp][0]), "r"(1u) : "memory");
        }
    }
}

// ---------------- FC: out = hs @ fc_w^T + fc_b  (round-7 proven config) ----
#define F_LD 72                        // halves per smem row (144 B)
#define F_TILE (128 * F_LD)            // halves per matrix tile
#define FC_NS 3
#define FC_SMEM (FC_NS * 2 * F_TILE * 2)   // 110592 B

__global__ void __launch_bounds__(256, 2) fc_kernel(
    const float* __restrict__ fc_b, float* __restrict__ out)
{
    extern __shared__ __half fsm[];
    const int tid = threadIdx.x, lane = tid & 31, w = tid >> 5;
    const int bm = blockIdx.x, bn = blockIdx.y;
    const int wm = (w >> 2) * 64, wn = (w & 3) * 32;

    const __half* Abase = g_hsh_pad + (size_t)Bc*Hc + (size_t)(bm*128)*Hc;
    const __half* Bbase = g_wh + (size_t)(bn*128)*Hc;

    float acc[4][4][4];
#pragma unroll
    for (int i=0;i<4;i++)
#pragma unroll
        for (int j=0;j<4;j++)
#pragma unroll
            for (int k=0;k<4;k++) acc[i][j][k]=0.f;

    auto load_stage = [&](int kt, int buf){
        __half* sA = fsm + buf * 2 * F_TILE;
        __half* sB = sA + F_TILE;
        const int k0 = kt * 64;
#pragma unroll
        for (int i = 0; i < 4; ++i) {
            int g = tid + i*256; int r = g >> 3, c = g & 7;
            cp16(saddr(sA + r*F_LD + c*8), Abase + (size_t)r*Hc + k0 + c*8);
        }
#pragma unroll
        for (int i = 0; i < 4; ++i) {
            int g = tid + i*256; int r = g >> 3, c = g & 7;
            cp16(saddr(sB + r*F_LD + c*8), Bbase + (size_t)r*Hc + k0 + c*8);
        }
        asm volatile("cp.async.commit_group;" ::: "memory");
    };

    load_stage(0, 0);
    load_stage(1, 1);

    for (int kt = 0; kt < 16; ++kt) {
        if (kt < 15) asm volatile("cp.async.wait_group 1;" ::: "memory");
        else         asm volatile("cp.async.wait_group 0;" ::: "memory");
        __syncthreads();
        // prefetch kt+2 into buffer freed at the sync above ((kt+2)%3 == (kt-1)%3)
        if (kt + 2 < 16) load_stage(kt + 2, (kt + 2) % FC_NS);

        const __half* sA = fsm + (kt % FC_NS) * 2 * F_TILE;
        const __half* sB = sA + F_TILE;
#pragma unroll
        for (int ks = 0; ks < 64; ks += 16) {
            uint32_t af[4][4], bf[4][2];
#pragma unroll
            for (int mt = 0; mt < 4; ++mt) {
                int row = wm + mt*16 + (lane & 7) + ((lane >> 3) & 1) * 8;
                int col = ks + (lane >> 4) * 8;
                ldm_x4(af[mt], saddr(sA + row*F_LD + col));
            }
#pragma unroll
            for (int nt = 0; nt < 4; ++nt) {
                int l = lane & 15;
                int row = wn + nt*8 + (l & 7);
                int col = ks + ((l >> 3) & 1) * 8;
                ldm_x2(bf[nt], saddr(sB + row*F_LD + col));
            }
#pragma unroll
            for (int mt = 0; mt < 4; ++mt)
#pragma unroll
                for (int nt = 0; nt < 4; ++nt)
                    mma_f16(acc[mt][nt], af[mt], bf[nt]);
        }
    }

#pragma unroll
    for (int nt = 0; nt < 4; ++nt) {
        int v = bn*128 + wn + nt*8 + (lane & 3)*2;
        float bia0 = fc_b[v], bia1 = fc_b[v+1];
#pragma unroll
        for (int mt = 0; mt < 4; ++mt) {
            int m = bm*128 + wm + mt*16 + (lane >> 2);
            int b0 = m & 31, t0 = m >> 5;
            *(float2*)(out + (size_t)(b0*Tc + t0)*Vc + v) =
                make_float2(acc[mt][nt][0]+bia0, acc[mt][nt][1]+bia1);
            int m2 = m + 8;
            int b1 = m2 & 31, t1 = m2 >> 5;
            *(float2*)(out + (size_t)(b1*Tc + t1)*Vc + v) =
                make_float2(acc[mt][nt][2]+bia0, acc[mt][nt][3]+bia1);
        }
    }
}

// ---------------- launch ----------------------------------------------------
extern "C" void kernel_launch(void* const* d_in, const int* in_sizes, int n_in,
                              void* d_out, int out_size)
{
    const int*   x     = (const int*)  d_in[0];
    const float* embed = (const float*)d_in[1];
    const float* W_ih  = (const float*)d_in[2];
    const float* W_hh  = (const float*)d_in[3];
    const float* b_ih  = (const float*)d_in[4];
    const float* b_hh  = (const float*)d_in[5];
    const float* fc_w  = (const float*)d_in[6];
    const float* fc_b  = (const float*)d_in[7];
    float* out = (float*)d_out;

    cudaFuncSetAttribute(lstm_kernel, cudaFuncAttributeMaxDynamicSharedMemorySize, LSTM_SMEM);
    cudaFuncSetAttribute(fc_kernel,   cudaFuncAttributeMaxDynamicSharedMemorySize, FC_SMEM);

    init_kernel<<<32, 256>>>();
    wh_prep_kernel<<<2048, 256>>>(fc_w);
    xg_kernel<<<dim3(32, 32), 256>>>(x, embed, W_ih, b_ih, b_hh);
    lstm_kernel<<<128, 256, LSTM_SMEM>>>(W_hh);
    fc_kernel<<<dim3(32, 250), 256, FC_SMEM>>>(fc_b, out);
}

// round 10
// speedup vs baseline: 1.0594x; 1.0276x over previous
#include <cuda_runtime.h>
#include <cuda_fp16.h>
#include <cstdint>

#define Bc 32
#define Tc 128
#define Ec 512
#define Hc 1024
#define Vc 32000
#define NTOK (Bc*Tc)      // 4096 tokens
#define G4H (4*Hc)        // 4096 gate rows

// ---------------- device scratch (no runtime alloc allowed) ----------------
__device__ float g_xg[(size_t)NTOK * G4H];                    // 64 MB
// padded h history: rows [0,32) = h_{-1} = 0; row (t+1)*32+b = h_t[b]
__device__ __align__(16) __half g_hsh_pad[(size_t)(NTOK + Bc) * Hc];
__device__ __align__(16) __half g_wh[(size_t)Vc * Hc];        // fc_w fp16 (64 MB)
__device__ unsigned int g_sync;

// ---------------- small helpers ----------------
static __device__ __forceinline__ uint32_t saddr(const void* p){
    return (uint32_t)__cvta_generic_to_shared(p);
}
static __device__ __forceinline__ void ldm_x4(uint32_t* r, uint32_t a){
    asm volatile("ldmatrix.sync.aligned.m8n8.x4.shared.b16 {%0,%1,%2,%3},[%4];"
        : "=r"(r[0]),"=r"(r[1]),"=r"(r[2]),"=r"(r[3]) : "r"(a));
}
static __device__ __forceinline__ void ldm_x2(uint32_t* r, uint32_t a){
    asm volatile("ldmatrix.sync.aligned.m8n8.x2.shared.b16 {%0,%1},[%2];"
        : "=r"(r[0]),"=r"(r[1]) : "r"(a));
}
static __device__ __forceinline__ void mma_f16(float* d, const uint32_t* a, const uint32_t* b){
    asm volatile("mma.sync.aligned.m16n8k16.row.col.f32.f16.f16.f32 "
        "{%0,%1,%2,%3},{%4,%5,%6,%7},{%8,%9},{%0,%1,%2,%3};"
        : "+f"(d[0]),"+f"(d[1]),"+f"(d[2]),"+f"(d[3])
        : "r"(a[0]),"r"(a[1]),"r"(a[2]),"r"(a[3]),"r"(b[0]),"r"(b[1]));
}
static __device__ __forceinline__ float sigmoidf_(float x){
    return 1.0f/(1.0f + __expf(-x));
}
static __device__ __forceinline__ void cp16(uint32_t dst, const void* src){
    asm volatile("cp.async.cg.shared.global [%0],[%1],16;\n" :: "r"(dst), "l"(src));
}

// ---------------- init: zero h_{-1} rows and sync counter (every replay) ---
__global__ void init_kernel(){
    int tid = blockIdx.x*blockDim.x + threadIdx.x;
    uint4* p = (uint4*)g_hsh_pad;               // first 32*Hc halves = 4096 uint4
    if (tid < 4096) p[tid] = make_uint4(0,0,0,0);
    if (tid == 0) g_sync = 0u;
}

// ---------------- prep: fc_w (f32) -> g_wh (fp16) ----------------
__global__ void __launch_bounds__(256) wh_prep_kernel(const float* __restrict__ fc_w){
    size_t total8 = (size_t)Vc * Hc / 8;
    size_t stride = (size_t)gridDim.x * blockDim.x;
    for (size_t g = blockIdx.x*(size_t)blockDim.x + threadIdx.x; g < total8; g += stride) {
        float4 v0 = *(const float4*)(fc_w + g*8);
        float4 v1 = *(const float4*)(fc_w + g*8 + 4);
        __half2 h0 = __float22half2_rn(make_float2(v0.x, v0.y));
        __half2 h1 = __float22half2_rn(make_float2(v0.z, v0.w));
        __half2 h2 = __float22half2_rn(make_float2(v1.x, v1.y));
        __half2 h3 = __float22half2_rn(make_float2(v1.z, v1.w));
        uint4 o;
        o.x = *(uint32_t*)&h0; o.y = *(uint32_t*)&h1;
        o.z = *(uint32_t*)&h2; o.w = *(uint32_t*)&h3;
        *(uint4*)(g_wh + g*8) = o;
    }
}

// ---------------- kernel A: xg = embed[x] @ W_ih^T + b_ih + b_hh (fp16) ----
#define A_BK 64
#define A_LD (A_BK + 8)

__global__ void __launch_bounds__(256) xg_kernel(
    const int* __restrict__ x, const float* __restrict__ embed,
    const float* __restrict__ W_ih, const float* __restrict__ b_ih,
    const float* __restrict__ b_hh)
{
    __shared__ __half sA[128 * A_LD];
    __shared__ __half sB[128 * A_LD];
    const int tid = threadIdx.x, lane = tid & 31, w = tid >> 5;
    const int bm = blockIdx.x, bn = blockIdx.y;
    const int wm = (w >> 2) * 64, wn = (w & 3) * 32;

    float acc[4][4][4];
#pragma unroll
    for (int i=0;i<4;i++)
#pragma unroll
        for (int j=0;j<4;j++)
#pragma unroll
            for (int k=0;k<4;k++) acc[i][j][k]=0.f;

    for (int kt = 0; kt < Ec / A_BK; ++kt) {
        const int k0 = kt * A_BK;
#pragma unroll
        for (int i = 0; i < 8; ++i) {
            int idx = tid + i*256;
            int r = idx >> 4, c4 = idx & 15;
            int m = bm*128 + r;
            int b = m & 31, t = m >> 5;
            int vid = x[b*Tc + t];
            float4 v = *(const float4*)(embed + (size_t)vid*Ec + k0 + c4*4);
            __half2* d = (__half2*)(sA + r*A_LD + c4*4);
            d[0] = __float22half2_rn(make_float2(v.x, v.y));
            d[1] = __float22half2_rn(make_float2(v.z, v.w));
        }
#pragma unroll
        for (int i = 0; i < 8; ++i) {
            int idx = tid + i*256;
            int r = idx >> 4, c4 = idx & 15;
            int n = bn*128 + r;
            float4 v = *(const float4*)(W_ih + (size_t)n*Ec + k0 + c4*4);
            __half2* d = (__half2*)(sB + r*A_LD + c4*4);
            d[0] = __float22half2_rn(make_float2(v.x, v.y));
            d[1] = __float22half2_rn(make_float2(v.z, v.w));
        }
        __syncthreads();
#pragma unroll
        for (int ks = 0; ks < A_BK; ks += 16) {
            uint32_t af[4][4], bf[4][2];
#pragma unroll
            for (int mt = 0; mt < 4; ++mt) {
                int row = wm + mt*16 + (lane & 7) + ((lane >> 3) & 1) * 8;
                int col = ks + (lane >> 4) * 8;
                ldm_x4(af[mt], saddr(sA + row*A_LD + col));
            }
#pragma unroll
            for (int nt = 0; nt < 4; ++nt) {
                int l = lane & 15;
                int row = wn + nt*8 + (l & 7);
                int col = ks + ((l >> 3) & 1) * 8;
                ldm_x2(bf[nt], saddr(sB + row*A_LD + col));
            }
#pragma unroll
            for (int mt = 0; mt < 4; ++mt)
#pragma unroll
                for (int nt = 0; nt < 4; ++nt)
                    mma_f16(acc[mt][nt], af[mt], bf[nt]);
        }
        __syncthreads();
    }
#pragma unroll
    for (int nt = 0; nt < 4; ++nt) {
        int col = bn*128 + wn + nt*8 + (lane & 3)*2;
        float bia0 = b_ih[col]   + b_hh[col];
        float bia1 = b_ih[col+1] + b_hh[col+1];
#pragma unroll
        for (int mt = 0; mt < 4; ++mt) {
            int row = bm*128 + wm + mt*16 + (lane >> 2);
            *(float2*)(g_xg + (size_t)row*G4H + col) =
                make_float2(acc[mt][nt][0]+bia0, acc[mt][nt][1]+bia1);
            *(float2*)(g_xg + (size_t)(row+8)*G4H + col) =
                make_float2(acc[mt][nt][2]+bia0, acc[mt][nt][3]+bia1);
        }
    }
}

// ---------------- recurrence: 128 CTAs x 256 thr (round-7 proven, exact) ---
#define L_LDH 1032                       // half row stride (2064 B)
#define L_SPW (32*34)                    // floats per warp partial tile
#define LSTM_SMEM (32*L_LDH*2 /*sW*/ + 32*L_LDH*2 /*sH*/ + 8*L_SPW*4 /*sP*/)

__global__ void __launch_bounds__(256, 1) lstm_kernel(const float* __restrict__ W_hh)
{
    extern __shared__ unsigned char smem[];
    __half* sW = (__half*)smem;                       // 32 x L_LDH (init only)
    __half* sH = sW + 32*L_LDH;                       // 32 x L_LDH
    float* sP = (float*)(sH + 32*L_LDH);              // 8 warps x 32 x 34
    const int tid = threadIdx.x, lane = tid & 31, w = tid >> 5;
    const int n = blockIdx.x;                // 0..127
    const int ub = tid & 7, bb = tid >> 3;   // this thread's (u, b) pair

    // one-time: W_hh slice (32 gate rows x 1024) fp32->fp16 into smem
    for (int idx = tid; idx < 32*256; idx += 256) {
        int r = idx >> 8, c4 = idx & 255;
        int gr = (r >> 3)*Hc + n*8 + (r & 7);
        float4 v = *(const float4*)(W_hh + (size_t)gr*Hc + c4*4);
        __half2* d = (__half2*)(sW + r*L_LDH + c4*4);
        d[0] = __float22half2_rn(make_float2(v.x, v.y));
        d[1] = __float22half2_rn(make_float2(v.z, v.w));
    }
    __syncthreads();

    // hoist W fragments into registers (reused for all 128 steps)
    uint32_t bw[8][4][2];
#pragma unroll
    for (int kt = 0; kt < 8; ++kt) {
        const int ks = w*128 + kt*16;
#pragma unroll
        for (int nt = 0; nt < 4; ++nt) {
            int l = lane & 15;
            int row = nt*8 + (l & 7);
            int col = ks + ((l >> 3) & 1) * 8;
            ldm_x2(bw[kt][nt], saddr(sW + row*L_LDH + col));
        }
    }
    float creg = 0.f;
    __syncthreads();

    for (int t = 0; t < Tc; ++t) {
        // prefetch xg for this thread's (b,u) — independent of h
        const float* xgp = g_xg + (size_t)(t*32 + bb)*G4H + n*8 + ub;
        float x0 = __ldcg(xgp);
        float x1 = __ldcg(xgp + Hc);
        float x2 = __ldcg(xgp + 2*Hc);
        float x3 = __ldcg(xgp + 3*Hc);

        // warp-private h slice load: warp w needs cols [128w, 128w+128) only
        {
            const __half* hsrc = g_hsh_pad + (size_t)(t*32)*Hc + w*128;
#pragma unroll
            for (int i = 0; i < 16; ++i) {
                int idx = i*32 + lane;          // 0..511
                int r = idx >> 4, cw = idx & 15;
                const uint4* gp = (const uint4*)(hsrc + (size_t)r*Hc + cw*8);
                uint4 v = __ldcg(gp);
                *(uint4*)(sH + r*L_LDH + w*128 + cw*8) = v;
            }
        }
        __syncwarp();

        // mma over this warp's K slice (A from smem via ldmatrix, W from regs)
        float acc[2][4][4];
#pragma unroll
        for (int i=0;i<2;i++)
#pragma unroll
            for (int j=0;j<4;j++)
#pragma unroll
                for (int k=0;k<4;k++) acc[i][j][k]=0.f;

#pragma unroll
        for (int kt = 0; kt < 8; ++kt) {
            const int ks = w*128 + kt*16;
            uint32_t af[2][4];
#pragma unroll
            for (int mt = 0; mt < 2; ++mt) {
                int row = mt*16 + (lane & 7) + ((lane >> 3) & 1) * 8;
                int col = ks + (lane >> 4) * 8;
                ldm_x4(af[mt], saddr(sH + row*L_LDH + col));
            }
#pragma unroll
            for (int mt = 0; mt < 2; ++mt)
#pragma unroll
                for (int nt = 0; nt < 4; ++nt)
                    mma_f16(acc[mt][nt], af[mt], bw[kt][nt]);
        }
        // dump partials: sP[w][row][col], stride 34
        float* sPw = sP + w*L_SPW;
#pragma unroll
        for (int mt = 0; mt < 2; ++mt)
#pragma unroll
            for (int nt = 0; nt < 4; ++nt) {
                int row = mt*16 + (lane >> 2);
                int col = nt*8 + (lane & 3)*2;
                *(float2*)(sPw + row*34 + col)     = make_float2(acc[mt][nt][0], acc[mt][nt][1]);
                *(float2*)(sPw + (row+8)*34 + col) = make_float2(acc[mt][nt][2], acc[mt][nt][3]);
            }
        __syncthreads();

        // reduce 8 partials + gate update; thread owns (bb, ub)
        float g0=0.f, g1=0.f, g2=0.f, g3=0.f;
#pragma unroll
        for (int ww = 0; ww < 8; ++ww) {
            const float* p = sP + ww*L_SPW + bb*34 + ub;
            g0 += p[0]; g1 += p[8]; g2 += p[16]; g3 += p[24];
        }
        float gi = sigmoidf_(g0 + x0);
        float gf = sigmoidf_(g1 + x1);
        float gg = tanhf   (g2 + x2);
        float go = sigmoidf_(g3 + x3);
        creg = gf * creg + gi * gg;
        float h = go * tanhf(creg);
        g_hsh_pad[(size_t)((t+1)*32 + bb)*Hc + n*8 + ub] = __float2half_rn(h);

        // 1-hop grid barrier: release-add + acquire poll on the counter
        __syncthreads();
        if (tid == 0) {
            asm volatile("red.release.gpu.global.add.u32 [%0], %1;"
                         :: "l"(&g_sync), "r"(1u) : "memory");
            unsigned f;
            const unsigned target = 128u*(unsigned)(t+1);
            do {
                asm volatile("ld.acquire.gpu.global.u32 %0, [%1];"
                             : "=r"(f) : "l"(&g_sync) : "memory");
            } while (f < target);
        }
        __syncthreads();
    }
}

// ---------------- FC: out = hs @ fc_w^T + fc_b ------------------------------
// CTA tile 128x128, 4 warps (2x2), warp tile 64x64, 3-stage, 2 CTAs/SM.
// Warp-tile 64x64 balances smem BW (0.031 B/FLOP) against the 128 B/cyc
// crossbar; 2 CTAs/SM hides the per-stage sync + cp.async wait bubbles.
#define F_LD 72                        // halves per smem row (144 B)
#define F_TILE (128 * F_LD)            // halves per matrix tile
#define FC_NS 3
#define FC_SMEM (FC_NS * 2 * F_TILE * 2)   // 110592 B

__global__ void __launch_bounds__(128, 2) fc_kernel(
    const float* __restrict__ fc_b, float* __restrict__ out)
{
    extern __shared__ __half fsm[];
    const int tid = threadIdx.x, lane = tid & 31, w = tid >> 5;
    const int bm = blockIdx.x, bn = blockIdx.y;
    const int wm = (w >> 1) * 64, wn = (w & 1) * 64;

    const __half* Abase = g_hsh_pad + (size_t)Bc*Hc + (size_t)(bm*128)*Hc;
    const __half* Bbase = g_wh + (size_t)(bn*128)*Hc;

    float acc[4][8][4];
#pragma unroll
    for (int i=0;i<4;i++)
#pragma unroll
        for (int j=0;j<8;j++)
#pragma unroll
            for (int k=0;k<4;k++) acc[i][j][k]=0.f;

    auto load_stage = [&](int kt, int buf){
        __half* sA = fsm + buf * 2 * F_TILE;
        __half* sB = sA + F_TILE;
        const int k0 = kt * 64;
#pragma unroll
        for (int i = 0; i < 8; ++i) {       // A: 1024 granules / 128 thr
            int g = tid + i*128; int r = g >> 3, c = g & 7;
            cp16(saddr(sA + r*F_LD + c*8), Abase + (size_t)r*Hc + k0 + c*8);
        }
#pragma unroll
        for (int i = 0; i < 8; ++i) {       // B: 1024 granules
            int g = tid + i*128; int r = g >> 3, c = g & 7;
            cp16(saddr(sB + r*F_LD + c*8), Bbase + (size_t)r*Hc + k0 + c*8);
        }
        asm volatile("cp.async.commit_group;" ::: "memory");
    };

    load_stage(0, 0);
    load_stage(1, 1);

    for (int kt = 0; kt < 16; ++kt) {
        if (kt < 15) asm volatile("cp.async.wait_group 1;" ::: "memory");
        else         asm volatile("cp.async.wait_group 0;" ::: "memory");
        __syncthreads();
        // prefetch kt+2 into buffer freed at the sync above
        if (kt + 2 < 16) load_stage(kt + 2, (kt + 2) % FC_NS);

        const __half* sA = fsm + (kt % FC_NS) * 2 * F_TILE;
        const __half* sB = sA + F_TILE;
#pragma unroll
        for (int ks = 0; ks < 64; ks += 16) {
            uint32_t af[4][4], bf[8][2];
#pragma unroll
            for (int mt = 0; mt < 4; ++mt) {
                int row = wm + mt*16 + (lane & 7) + ((lane >> 3) & 1) * 8;
                int col = ks + (lane >> 4) * 8;
                ldm_x4(af[mt], saddr(sA + row*F_LD + col));
            }
#pragma unroll
            for (int nt = 0; nt < 8; ++nt) {
                int l = lane & 15;
                int row = wn + nt*8 + (l & 7);
                int col = ks + ((l >> 3) & 1) * 8;
                ldm_x2(bf[nt], saddr(sB + row*F_LD + col));
            }
#pragma unroll
            for (int mt = 0; mt < 4; ++mt)
#pragma unroll
                for (int nt = 0; nt < 8; ++nt)
                    mma_f16(acc[mt][nt], af[mt], bf[nt]);
        }
    }

    // epilogue: + fc_b, scatter m=t*32+b -> out[(b*T+t)*V + v]
#pragma unroll
    for (int nt = 0; nt < 8; ++nt) {
        int v = bn*128 + wn + nt*8 + (lane & 3)*2;
        float bia0 = fc_b[v], bia1 = fc_b[v+1];
#pragma unroll
        for (int mt = 0; mt < 4; ++mt) {
            int m = bm*128 + wm + mt*16 + (lane >> 2);
            int b0 = m & 31, t0 = m >> 5;
            *(float2*)(out + (size_t)(b0*Tc + t0)*Vc + v) =
                make_float2(acc[mt][nt][0]+bia0, acc[mt][nt][1]+bia1);
            int m2 = m + 8;
            int b1 = m2 & 31, t1 = m2 >> 5;
            *(float2*)(out + (size_t)(b1*Tc + t1)*Vc + v) =
                make_float2(acc[mt][nt][2]+bia0, acc[mt][nt][3]+bia1);
        }
    }
}

// ---------------- launch ----------------------------------------------------
extern "C" void kernel_launch(void* const* d_in, const int* in_sizes, int n_in,
                              void* d_out, int out_size)
{
    const int*   x     = (const int*)  d_in[0];
    const float* embed = (const float*)d_in[1];
    const float* W_ih  = (const float*)d_in[2];
    const float* W_hh  = (const float*)d_in[3];
    const float* b_ih  = (const float*)d_in[4];
    const float* b_hh  = (const float*)d_in[5];
    const float* fc_w  = (const float*)d_in[6];
    const float* fc_b  = (const float*)d_in[7];
    float* out = (float*)d_out;

    cudaFuncSetAttribute(lstm_kernel, cudaFuncAttributeMaxDynamicSharedMemorySize, LSTM_SMEM);
    cudaFuncSetAttribute(fc_kernel,   cudaFuncAttributeMaxDynamicSharedMemorySize, FC_SMEM);

    init_kernel<<<32, 256>>>();
    wh_prep_kernel<<<2048, 256>>>(fc_w);
    xg_kernel<<<dim3(32, 32), 256>>>(x, embed, W_ih, b_ih, b_hh);
    lstm_kernel<<<128, 256, LSTM_SMEM>>>(W_hh);
    fc_kernel<<<dim3(32, 250), 128, FC_SMEM>>>(fc_b, out);
}

// round 11
// speedup vs baseline: 1.0685x; 1.0085x over previous
#include <cuda_runtime.h>
#include <cuda_fp16.h>
#include <cstdint>

#define Bc 32
#define Tc 128
#define Ec 512
#define Hc 1024
#define Vc 32000
#define NTOK (Bc*Tc)      // 4096 tokens
#define G4H (4*Hc)        // 4096 gate rows

// ---------------- device scratch (no runtime alloc allowed) ----------------
__device__ float g_xg[(size_t)NTOK * G4H];                    // 64 MB
// padded h history: rows [0,32) = h_{-1} = 0; row (t+1)*32+b = h_t[b]
__device__ __align__(16) __half g_hsh_pad[(size_t)(NTOK + Bc) * Hc];
__device__ __align__(16) __half g_wh[(size_t)Vc * Hc];        // fc_w fp16 (64 MB)
__device__ unsigned int g_sync;

// ---------------- small helpers ----------------
static __device__ __forceinline__ uint32_t saddr(const void* p){
    return (uint32_t)__cvta_generic_to_shared(p);
}
static __device__ __forceinline__ void ldm_x4(uint32_t* r, uint32_t a){
    asm volatile("ldmatrix.sync.aligned.m8n8.x4.shared.b16 {%0,%1,%2,%3},[%4];"
        : "=r"(r[0]),"=r"(r[1]),"=r"(r[2]),"=r"(r[3]) : "r"(a));
}
static __device__ __forceinline__ void ldm_x2(uint32_t* r, uint32_t a){
    asm volatile("ldmatrix.sync.aligned.m8n8.x2.shared.b16 {%0,%1},[%2];"
        : "=r"(r[0]),"=r"(r[1]) : "r"(a));
}
static __device__ __forceinline__ void mma_f16(float* d, const uint32_t* a, const uint32_t* b){
    asm volatile("mma.sync.aligned.m16n8k16.row.col.f32.f16.f16.f32 "
        "{%0,%1,%2,%3},{%4,%5,%6,%7},{%8,%9},{%0,%1,%2,%3};"
        : "+f"(d[0]),"+f"(d[1]),"+f"(d[2]),"+f"(d[3])
        : "r"(a[0]),"r"(a[1]),"r"(a[2]),"r"(a[3]),"r"(b[0]),"r"(b[1]));
}
static __device__ __forceinline__ float sigmoidf_(float x){
    return 1.0f/(1.0f + __expf(-x));
}
static __device__ __forceinline__ void cp16(uint32_t dst, const void* src){
    asm volatile("cp.async.cg.shared.global [%0],[%1],16;\n" :: "r"(dst), "l"(src));
}

// ---------------- init: zero h_{-1} rows and sync counter (every replay) ---
__global__ void init_kernel(){
    int tid = blockIdx.x*blockDim.x + threadIdx.x;
    uint4* p = (uint4*)g_hsh_pad;               // first 32*Hc halves = 4096 uint4
    if (tid < 4096) p[tid] = make_uint4(0,0,0,0);
    if (tid == 0) g_sync = 0u;
}

// ---------------- fused: xg GEMM (CTAs 0..1023) + fc_w->fp16 (CTAs 1024+) --
#define A_BK 64
#define A_LD (A_BK + 8)
#define PREP_CTAS 512

__global__ void __launch_bounds__(256) xgprep_kernel(
    const int* __restrict__ x, const float* __restrict__ embed,
    const float* __restrict__ W_ih, const float* __restrict__ b_ih,
    const float* __restrict__ b_hh, const float* __restrict__ fc_w)
{
    __shared__ __half sA[128 * A_LD];
    __shared__ __half sB[128 * A_LD];
    const int tid = threadIdx.x;

    if (blockIdx.x >= 1024) {
        // ---- prep path: fc_w (f32) -> g_wh (fp16) ----
        size_t total8 = (size_t)Vc * Hc / 8;
        size_t stride = (size_t)PREP_CTAS * 256;
        for (size_t g = (blockIdx.x - 1024)*(size_t)256 + tid; g < total8; g += stride) {
            float4 v0 = *(const float4*)(fc_w + g*8);
            float4 v1 = *(const float4*)(fc_w + g*8 + 4);
            __half2 h0 = __float22half2_rn(make_float2(v0.x, v0.y));
            __half2 h1 = __float22half2_rn(make_float2(v0.z, v0.w));
            __half2 h2 = __float22half2_rn(make_float2(v1.x, v1.y));
            __half2 h3 = __float22half2_rn(make_float2(v1.z, v1.w));
            uint4 o;
            o.x = *(uint32_t*)&h0; o.y = *(uint32_t*)&h1;
            o.z = *(uint32_t*)&h2; o.w = *(uint32_t*)&h3;
            *(uint4*)(g_wh + g*8) = o;
        }
        return;
    }

    // ---- xg path: xg = embed[x] @ W_ih^T + b_ih + b_hh (fp16 mma) ----
    const int lane = tid & 31, w = tid >> 5;
    const int bm = blockIdx.x & 31, bn = blockIdx.x >> 5;
    const int wm = (w >> 2) * 64, wn = (w & 3) * 32;

    float acc[4][4][4];
#pragma unroll
    for (int i=0;i<4;i++)
#pragma unroll
        for (int j=0;j<4;j++)
#pragma unroll
            for (int k=0;k<4;k++) acc[i][j][k]=0.f;

    for (int kt = 0; kt < Ec / A_BK; ++kt) {
        const int k0 = kt * A_BK;
#pragma unroll
        for (int i = 0; i < 8; ++i) {
            int idx = tid + i*256;
            int r = idx >> 4, c4 = idx & 15;
            int m = bm*128 + r;
            int b = m & 31, t = m >> 5;
            int vid = x[b*Tc + t];
            float4 v = *(const float4*)(embed + (size_t)vid*Ec + k0 + c4*4);
            __half2* d = (__half2*)(sA + r*A_LD + c4*4);
            d[0] = __float22half2_rn(make_float2(v.x, v.y));
            d[1] = __float22half2_rn(make_float2(v.z, v.w));
        }
#pragma unroll
        for (int i = 0; i < 8; ++i) {
            int idx = tid + i*256;
            int r = idx >> 4, c4 = idx & 15;
            int n = bn*128 + r;
            float4 v = *(const float4*)(W_ih + (size_t)n*Ec + k0 + c4*4);
            __half2* d = (__half2*)(sB + r*A_LD + c4*4);
            d[0] = __float22half2_rn(make_float2(v.x, v.y));
            d[1] = __float22half2_rn(make_float2(v.z, v.w));
        }
        __syncthreads();
#pragma unroll
        for (int ks = 0; ks < A_BK; ks += 16) {
            uint32_t af[4][4], bf[4][2];
#pragma unroll
            for (int mt = 0; mt < 4; ++mt) {
                int row = wm + mt*16 + (lane & 7) + ((lane >> 3) & 1) * 8;
                int col = ks + (lane >> 4) * 8;
                ldm_x4(af[mt], saddr(sA + row*A_LD + col));
            }
#pragma unroll
            for (int nt = 0; nt < 4; ++nt) {
                int l = lane & 15;
                int row = wn + nt*8 + (l & 7);
                int col = ks + ((l >> 3) & 1) * 8;
                ldm_x2(bf[nt], saddr(sB + row*A_LD + col));
            }
#pragma unroll
            for (int mt = 0; mt < 4; ++mt)
#pragma unroll
                for (int nt = 0; nt < 4; ++nt)
                    mma_f16(acc[mt][nt], af[mt], bf[nt]);
        }
        __syncthreads();
    }
#pragma unroll
    for (int nt = 0; nt < 4; ++nt) {
        int col = bn*128 + wn + nt*8 + (lane & 3)*2;
        float bia0 = b_ih[col]   + b_hh[col];
        float bia1 = b_ih[col+1] + b_hh[col+1];
#pragma unroll
        for (int mt = 0; mt < 4; ++mt) {
            int row = bm*128 + wm + mt*16 + (lane >> 2);
            *(float2*)(g_xg + (size_t)row*G4H + col) =
                make_float2(acc[mt][nt][0]+bia0, acc[mt][nt][1]+bia1);
            *(float2*)(g_xg + (size_t)(row+8)*G4H + col) =
                make_float2(acc[mt][nt][2]+bia0, acc[mt][nt][3]+bia1);
        }
    }
}

// ---------------- recurrence: 128 CTAs x 256 thr (round-7 proven, exact) ---
#define L_LDH 1032                       // half row stride (2064 B)
#define L_SPW (32*34)                    // floats per warp partial tile
#define LSTM_SMEM (32*L_LDH*2 /*sW*/ + 32*L_LDH*2 /*sH*/ + 8*L_SPW*4 /*sP*/)

__global__ void __launch_bounds__(256, 1) lstm_kernel(const float* __restrict__ W_hh)
{
    extern __shared__ unsigned char smem[];
    __half* sW = (__half*)smem;                       // 32 x L_LDH (init only)
    __half* sH = sW + 32*L_LDH;                       // 32 x L_LDH
    float* sP = (float*)(sH + 32*L_LDH);              // 8 warps x 32 x 34
    const int tid = threadIdx.x, lane = tid & 31, w = tid >> 5;
    const int n = blockIdx.x;                // 0..127
    const int ub = tid & 7, bb = tid >> 3;   // this thread's (u, b) pair

    // one-time: W_hh slice (32 gate rows x 1024) fp32->fp16 into smem
    for (int idx = tid; idx < 32*256; idx += 256) {
        int r = idx >> 8, c4 = idx & 255;
        int gr = (r >> 3)*Hc + n*8 + (r & 7);
        float4 v = *(const float4*)(W_hh + (size_t)gr*Hc + c4*4);
        __half2* d = (__half2*)(sW + r*L_LDH + c4*4);
        d[0] = __float22half2_rn(make_float2(v.x, v.y));
        d[1] = __float22half2_rn(make_float2(v.z, v.w));
    }
    __syncthreads();

    // hoist W fragments into registers (reused for all 128 steps)
    uint32_t bw[8][4][2];
#pragma unroll
    for (int kt = 0; kt < 8; ++kt) {
        const int ks = w*128 + kt*16;
#pragma unroll
        for (int nt = 0; nt < 4; ++nt) {
            int l = lane & 15;
            int row = nt*8 + (l & 7);
            int col = ks + ((l >> 3) & 1) * 8;
            ldm_x2(bw[kt][nt], saddr(sW + row*L_LDH + col));
        }
    }
    float creg = 0.f;
    __syncthreads();

    for (int t = 0; t < Tc; ++t) {
        // prefetch xg for this thread's (b,u) — independent of h
        const float* xgp = g_xg + (size_t)(t*32 + bb)*G4H + n*8 + ub;
        float x0 = __ldcg(xgp);
        float x1 = __ldcg(xgp + Hc);
        float x2 = __ldcg(xgp + 2*Hc);
        float x3 = __ldcg(xgp + 3*Hc);

        // warp-private h slice load: warp w needs cols [128w, 128w+128) only
        {
            const __half* hsrc = g_hsh_pad + (size_t)(t*32)*Hc + w*128;
#pragma unroll
            for (int i = 0; i < 16; ++i) {
                int idx = i*32 + lane;          // 0..511
                int r = idx >> 4, cw = idx & 15;
                const uint4* gp = (const uint4*)(hsrc + (size_t)r*Hc + cw*8);
                uint4 v = __ldcg(gp);
                *(uint4*)(sH + r*L_LDH + w*128 + cw*8) = v;
            }
        }
        __syncwarp();

        // mma over this warp's K slice (A from smem via ldmatrix, W from regs)
        float acc[2][4][4];
#pragma unroll
        for (int i=0;i<2;i++)
#pragma unroll
            for (int j=0;j<4;j++)
#pragma unroll
                for (int k=0;k<4;k++) acc[i][j][k]=0.f;

#pragma unroll
        for (int kt = 0; kt < 8; ++kt) {
            const int ks = w*128 + kt*16;
            uint32_t af[2][4];
#pragma unroll
            for (int mt = 0; mt < 2; ++mt) {
                int row = mt*16 + (lane & 7) + ((lane >> 3) & 1) * 8;
                int col = ks + (lane >> 4) * 8;
                ldm_x4(af[mt], saddr(sH + row*L_LDH + col));
            }
#pragma unroll
            for (int mt = 0; mt < 2; ++mt)
#pragma unroll
                for (int nt = 0; nt < 4; ++nt)
                    mma_f16(acc[mt][nt], af[mt], bw[kt][nt]);
        }
        // dump partials: sP[w][row][col], stride 34
        float* sPw = sP + w*L_SPW;
#pragma unroll
        for (int mt = 0; mt < 2; ++mt)
#pragma unroll
            for (int nt = 0; nt < 4; ++nt) {
                int row = mt*16 + (lane >> 2);
                int col = nt*8 + (lane & 3)*2;
                *(float2*)(sPw + row*34 + col)     = make_float2(acc[mt][nt][0], acc[mt][nt][1]);
                *(float2*)(sPw + (row+8)*34 + col) = make_float2(acc[mt][nt][2], acc[mt][nt][3]);
            }
        __syncthreads();

        // reduce 8 partials + gate update; thread owns (bb, ub)
        float g0=0.f, g1=0.f, g2=0.f, g3=0.f;
#pragma unroll
        for (int ww = 0; ww < 8; ++ww) {
            const float* p = sP + ww*L_SPW + bb*34 + ub;
            g0 += p[0]; g1 += p[8]; g2 += p[16]; g3 += p[24];
        }
        float gi = sigmoidf_(g0 + x0);
        float gf = sigmoidf_(g1 + x1);
        float gg = tanhf   (g2 + x2);
        float go = sigmoidf_(g3 + x3);
        creg = gf * creg + gi * gg;
        float h = go * tanhf(creg);
        g_hsh_pad[(size_t)((t+1)*32 + bb)*Hc + n*8 + ub] = __float2half_rn(h);

        // 1-hop grid barrier (skipped on the final step; kernel-end syncs)
        __syncthreads();
        if (t + 1 < Tc) {
            if (tid == 0) {
                asm volatile("red.release.gpu.global.add.u32 [%0], %1;"
                             :: "l"(&g_sync), "r"(1u) : "memory");
                unsigned f;
                const unsigned target = 128u*(unsigned)(t+1);
                do {
                    asm volatile("ld.acquire.gpu.global.u32 %0, [%1];"
                                 : "=r"(f) : "l"(&g_sync) : "memory");
                } while (f < target);
            }
            __syncthreads();
        }
    }
}

// ---------------- FC: out = hs @ fc_w^T + fc_b ------------------------------
// CTA tile 128x128, 4 warps (2x2), warp tile 64x64, 3-stage, 2 CTAs/SM.
// Fragment double-buffering: LDSM for ks+1 issues under HMMA for ks.
#define F_LD 72                        // halves per smem row (144 B)
#define F_TILE (128 * F_LD)            // halves per matrix tile
#define FC_NS 3
#define FC_SMEM (FC_NS * 2 * F_TILE * 2)   // 110592 B

__global__ void __launch_bounds__(128, 2) fc_kernel(
    const float* __restrict__ fc_b, float* __restrict__ out)
{
    extern __shared__ __half fsm[];
    const int tid = threadIdx.x, lane = tid & 31, w = tid >> 5;
    const int bm = blockIdx.x, bn = blockIdx.y;
    const int wm = (w >> 1) * 64, wn = (w & 1) * 64;

    const __half* Abase = g_hsh_pad + (size_t)Bc*Hc + (size_t)(bm*128)*Hc;
    const __half* Bbase = g_wh + (size_t)(bn*128)*Hc;

    float acc[4][8][4];
#pragma unroll
    for (int i=0;i<4;i++)
#pragma unroll
        for (int j=0;j<8;j++)
#pragma unroll
            for (int k=0;k<4;k++) acc[i][j][k]=0.f;

    auto load_stage = [&](int kt, int buf){
        __half* sA = fsm + buf * 2 * F_TILE;
        __half* sB = sA + F_TILE;
        const int k0 = kt * 64;
#pragma unroll
        for (int i = 0; i < 8; ++i) {       // A: 1024 granules / 128 thr
            int g = tid + i*128; int r = g >> 3, c = g & 7;
            cp16(saddr(sA + r*F_LD + c*8), Abase + (size_t)r*Hc + k0 + c*8);
        }
#pragma unroll
        for (int i = 0; i < 8; ++i) {       // B: 1024 granules
            int g = tid + i*128; int r = g >> 3, c = g & 7;
            cp16(saddr(sB + r*F_LD + c*8), Bbase + (size_t)r*Hc + k0 + c*8);
        }
        asm volatile("cp.async.commit_group;" ::: "memory");
    };

    load_stage(0, 0);
    load_stage(1, 1);

    for (int kt = 0; kt < 16; ++kt) {
        if (kt < 15) asm volatile("cp.async.wait_group 1;" ::: "memory");
        else         asm volatile("cp.async.wait_group 0;" ::: "memory");
        __syncthreads();
        // prefetch kt+2 into buffer freed at the sync above
        if (kt + 2 < 16) load_stage(kt + 2, (kt + 2) % FC_NS);

        const __half* sA = fsm + (kt % FC_NS) * 2 * F_TILE;
        const __half* sB = sA + F_TILE;

        uint32_t af[2][4][4], bf[2][8][2];
        auto frag_load = [&](int buf, int ks){
#pragma unroll
            for (int mt = 0; mt < 4; ++mt) {
                int row = wm + mt*16 + (lane & 7) + ((lane >> 3) & 1) * 8;
                int col = ks + (lane >> 4) * 8;
                ldm_x4(af[buf][mt], saddr(sA + row*F_LD + col));
            }
#pragma unroll
            for (int nt = 0; nt < 8; ++nt) {
                int l = lane & 15;
                int row = wn + nt*8 + (l & 7);
                int col = ks + ((l >> 3) & 1) * 8;
                ldm_x2(bf[buf][nt], saddr(sB + row*F_LD + col));
            }
        };

        frag_load(0, 0);
#pragma unroll
        for (int ksi = 0; ksi < 4; ++ksi) {
            const int cur = ksi & 1;
            if (ksi < 3) frag_load(cur ^ 1, (ksi + 1) * 16);
#pragma unroll
            for (int mt = 0; mt < 4; ++mt)
#pragma unroll
                for (int nt = 0; nt < 8; ++nt)
                    mma_f16(acc[mt][nt], af[cur][mt], bf[cur][nt]);
        }
    }

    // epilogue: + fc_b, scatter m=t*32+b -> out[(b*T+t)*V + v]
#pragma unroll
    for (int nt = 0; nt < 8; ++nt) {
        int v = bn*128 + wn + nt*8 + (lane & 3)*2;
        float bia0 = fc_b[v], bia1 = fc_b[v+1];
#pragma unroll
        for (int mt = 0; mt < 4; ++mt) {
            int m = bm*128 + wm + mt*16 + (lane >> 2);
            int b0 = m & 31, t0 = m >> 5;
            *(float2*)(out + (size_t)(b0*Tc + t0)*Vc + v) =
                make_float2(acc[mt][nt][0]+bia0, acc[mt][nt][1]+bia1);
            int m2 = m + 8;
            int b1 = m2 & 31, t1 = m2 >> 5;
            *(float2*)(out + (size_t)(b1*Tc + t1)*Vc + v) =
                make_float2(acc[mt][nt][2]+bia0, acc[mt][nt][3]+bia1);
        }
    }
}

// ---------------- launch ----------------------------------------------------
extern "C" void kernel_launch(void* const* d_in, const int* in_sizes, int n_in,
                              void* d_out, int out_size)
{
    const int*   x     = (const int*)  d_in[0];
    const float* embed = (const float*)d_in[1];
    const float* W_ih  = (const float*)d_in[2];
    const float* W_hh  = (const float*)d_in[3];
    const float* b_ih  = (const float*)d_in[4];
    const float* b_hh  = (const float*)d_in[5];
    const float* fc_w  = (const float*)d_in[6];
    const float* fc_b  = (const float*)d_in[7];
    float* out = (float*)d_out;

    cudaFuncSetAttribute(lstm_kernel, cudaFuncAttributeMaxDynamicSharedMemorySize, LSTM_SMEM);
    cudaFuncSetAttribute(fc_kernel,   cudaFuncAttributeMaxDynamicSharedMemorySize, FC_SMEM);

    init_kernel<<<32, 256>>>();
    xgprep_kernel<<<1024 + PREP_CTAS, 256>>>(x, embed, W_ih, b_ih, b_hh, fc_w);
    lstm_kernel<<<128, 256, LSTM_SMEM>>>(W_hh);
    fc_kernel<<<dim3(32, 250), 128, FC_SMEM>>>(fc_b, out);
}

// round 12
// speedup vs baseline: 1.1070x; 1.0361x over previous
#include <cuda_runtime.h>
#include <cuda_fp16.h>
#include <cstdint>

#define Bc 32
#define Tc 128
#define Ec 512
#define Hc 1024
#define Vc 32000
#define NTOK (Bc*Tc)      // 4096 tokens
#define G4H (4*Hc)        // 4096 gate rows

// ---------------- device scratch (no runtime alloc allowed) ----------------
__device__ float g_xg[(size_t)NTOK * G4H];                    // 64 MB
// padded h history: rows [0,32) = h_{-1} = 0; row (t+1)*32+b = h_t[b]
__device__ __align__(16) __half g_hsh_pad[(size_t)(NTOK + Bc) * Hc];
__device__ __align__(16) __half g_wh[(size_t)Vc * Hc];        // fc_w fp16 (64 MB)
__device__ unsigned int g_sync;

// ---------------- small helpers ----------------
static __device__ __forceinline__ uint32_t saddr(const void* p){
    return (uint32_t)__cvta_generic_to_shared(p);
}
static __device__ __forceinline__ void ldm_x4(uint32_t* r, uint32_t a){
    asm volatile("ldmatrix.sync.aligned.m8n8.x4.shared.b16 {%0,%1,%2,%3},[%4];"
        : "=r"(r[0]),"=r"(r[1]),"=r"(r[2]),"=r"(r[3]) : "r"(a));
}
static __device__ __forceinline__ void ldm_x2(uint32_t* r, uint32_t a){
    asm volatile("ldmatrix.sync.aligned.m8n8.x2.shared.b16 {%0,%1},[%2];"
        : "=r"(r[0]),"=r"(r[1]) : "r"(a));
}
static __device__ __forceinline__ void mma_f16(float* d, const uint32_t* a, const uint32_t* b){
    asm volatile("mma.sync.aligned.m16n8k16.row.col.f32.f16.f16.f32 "
        "{%0,%1,%2,%3},{%4,%5,%6,%7},{%8,%9},{%0,%1,%2,%3};"
        : "+f"(d[0]),"+f"(d[1]),"+f"(d[2]),"+f"(d[3])
        : "r"(a[0]),"r"(a[1]),"r"(a[2]),"r"(a[3]),"r"(b[0]),"r"(b[1]));
}
static __device__ __forceinline__ float sigmoidf_(float x){
    return 1.0f/(1.0f + __expf(-x));
}
static __device__ __forceinline__ void cp16(uint32_t dst, const void* src){
    asm volatile("cp.async.cg.shared.global [%0],[%1],16;\n" :: "r"(dst), "l"(src));
}

// ---------------- init: zero h_{-1} rows and sync counter (every replay) ---
__global__ void init_kernel(){
    int tid = blockIdx.x*blockDim.x + threadIdx.x;
    uint4* p = (uint4*)g_hsh_pad;               // first 32*Hc halves = 4096 uint4
    if (tid < 4096) p[tid] = make_uint4(0,0,0,0);
    if (tid == 0) g_sync = 0u;
}

// ---------------- fused: xg GEMM (CTAs 0..1023) + fc_w->fp16 (CTAs 1024+) --
#define A_BK 64
#define A_LD (A_BK + 8)
#define PREP_CTAS 512

__global__ void __launch_bounds__(256) xgprep_kernel(
    const int* __restrict__ x, const float* __restrict__ embed,
    const float* __restrict__ W_ih, const float* __restrict__ b_ih,
    const float* __restrict__ b_hh, const float* __restrict__ fc_w)
{
    __shared__ __half sA[128 * A_LD];
    __shared__ __half sB[128 * A_LD];
    const int tid = threadIdx.x;

    if (blockIdx.x >= 1024) {
        // ---- prep path: fc_w (f32) -> g_wh (fp16) ----
        size_t total8 = (size_t)Vc * Hc / 8;
        size_t stride = (size_t)PREP_CTAS * 256;
        for (size_t g = (blockIdx.x - 1024)*(size_t)256 + tid; g < total8; g += stride) {
            float4 v0 = *(const float4*)(fc_w + g*8);
            float4 v1 = *(const float4*)(fc_w + g*8 + 4);
            __half2 h0 = __float22half2_rn(make_float2(v0.x, v0.y));
            __half2 h1 = __float22half2_rn(make_float2(v0.z, v0.w));
            __half2 h2 = __float22half2_rn(make_float2(v1.x, v1.y));
            __half2 h3 = __float22half2_rn(make_float2(v1.z, v1.w));
            uint4 o;
            o.x = *(uint32_t*)&h0; o.y = *(uint32_t*)&h1;
            o.z = *(uint32_t*)&h2; o.w = *(uint32_t*)&h3;
            *(uint4*)(g_wh + g*8) = o;
        }
        return;
    }

    // ---- xg path: xg = embed[x] @ W_ih^T + b_ih + b_hh (fp16 mma) ----
    const int lane = tid & 31, w = tid >> 5;
    const int bm = blockIdx.x & 31, bn = blockIdx.x >> 5;
    const int wm = (w >> 2) * 64, wn = (w & 3) * 32;

    float acc[4][4][4];
#pragma unroll
    for (int i=0;i<4;i++)
#pragma unroll
        for (int j=0;j<4;j++)
#pragma unroll
            for (int k=0;k<4;k++) acc[i][j][k]=0.f;

    for (int kt = 0; kt < Ec / A_BK; ++kt) {
        const int k0 = kt * A_BK;
#pragma unroll
        for (int i = 0; i < 8; ++i) {
            int idx = tid + i*256;
            int r = idx >> 4, c4 = idx & 15;
            int m = bm*128 + r;
            int b = m & 31, t = m >> 5;
            int vid = x[b*Tc + t];
            float4 v = *(const float4*)(embed + (size_t)vid*Ec + k0 + c4*4);
            __half2* d = (__half2*)(sA + r*A_LD + c4*4);
            d[0] = __float22half2_rn(make_float2(v.x, v.y));
            d[1] = __float22half2_rn(make_float2(v.z, v.w));
        }
#pragma unroll
        for (int i = 0; i < 8; ++i) {
            int idx = tid + i*256;
            int r = idx >> 4, c4 = idx & 15;
            int n = bn*128 + r;
            float4 v = *(const float4*)(W_ih + (size_t)n*Ec + k0 + c4*4);
            __half2* d = (__half2*)(sB + r*A_LD + c4*4);
            d[0] = __float22half2_rn(make_float2(v.x, v.y));
            d[1] = __float22half2_rn(make_float2(v.z, v.w));
        }
        __syncthreads();
#pragma unroll
        for (int ks = 0; ks < A_BK; ks += 16) {
            uint32_t af[4][4], bf[4][2];
#pragma unroll
            for (int mt = 0; mt < 4; ++mt) {
                int row = wm + mt*16 + (lane & 7) + ((lane >> 3) & 1) * 8;
                int col = ks + (lane >> 4) * 8;
                ldm_x4(af[mt], saddr(sA + row*A_LD + col));
            }
#pragma unroll
            for (int nt = 0; nt < 4; ++nt) {
                int l = lane & 15;
                int row = wn + nt*8 + (l & 7);
                int col = ks + ((l >> 3) & 1) * 8;
                ldm_x2(bf[nt], saddr(sB + row*A_LD + col));
            }
#pragma unroll
            for (int mt = 0; mt < 4; ++mt)
#pragma unroll
                for (int nt = 0; nt < 4; ++nt)
                    mma_f16(acc[mt][nt], af[mt], bf[nt]);
        }
        __syncthreads();
    }
#pragma unroll
    for (int nt = 0; nt < 4; ++nt) {
        int col = bn*128 + wn + nt*8 + (lane & 3)*2;
        float bia0 = b_ih[col]   + b_hh[col];
        float bia1 = b_ih[col+1] + b_hh[col+1];
#pragma unroll
        for (int mt = 0; mt < 4; ++mt) {
            int row = bm*128 + wm + mt*16 + (lane >> 2);
            *(float2*)(g_xg + (size_t)row*G4H + col) =
                make_float2(acc[mt][nt][0]+bia0, acc[mt][nt][1]+bia1);
            *(float2*)(g_xg + (size_t)(row+8)*G4H + col) =
                make_float2(acc[mt][nt][2]+bia0, acc[mt][nt][3]+bia1);
        }
    }
}

// ---------------- recurrence: 128 CTAs x 256 thr (round-7 proven, exact) ---
#define L_LDH 1032                       // half row stride (2064 B)
#define L_SPW (32*34)                    // floats per warp partial tile
#define LSTM_SMEM (32*L_LDH*2 /*sW*/ + 32*L_LDH*2 /*sH*/ + 8*L_SPW*4 /*sP*/)

__global__ void __launch_bounds__(256, 1) lstm_kernel(const float* __restrict__ W_hh)
{
    extern __shared__ unsigned char smem[];
    __half* sW = (__half*)smem;                       // 32 x L_LDH (init only)
    __half* sH = sW + 32*L_LDH;                       // 32 x L_LDH
    float* sP = (float*)(sH + 32*L_LDH);              // 8 warps x 32 x 34
    const int tid = threadIdx.x, lane = tid & 31, w = tid >> 5;
    const int n = blockIdx.x;                // 0..127
    const int ub = tid & 7, bb = tid >> 3;   // this thread's (u, b) pair

    // one-time: W_hh slice (32 gate rows x 1024) fp32->fp16 into smem
    for (int idx = tid; idx < 32*256; idx += 256) {
        int r = idx >> 8, c4 = idx & 255;
        int gr = (r >> 3)*Hc + n*8 + (r & 7);
        float4 v = *(const float4*)(W_hh + (size_t)gr*Hc + c4*4);
        __half2* d = (__half2*)(sW + r*L_LDH + c4*4);
        d[0] = __float22half2_rn(make_float2(v.x, v.y));
        d[1] = __float22half2_rn(make_float2(v.z, v.w));
    }
    __syncthreads();

    // hoist W fragments into registers (reused for all 128 steps)
    uint32_t bw[8][4][2];
#pragma unroll
    for (int kt = 0; kt < 8; ++kt) {
        const int ks = w*128 + kt*16;
#pragma unroll
        for (int nt = 0; nt < 4; ++nt) {
            int l = lane & 15;
            int row = nt*8 + (l & 7);
            int col = ks + ((l >> 3) & 1) * 8;
            ldm_x2(bw[kt][nt], saddr(sW + row*L_LDH + col));
        }
    }
    float creg = 0.f;
    __syncthreads();

    for (int t = 0; t < Tc; ++t) {
        // prefetch xg for this thread's (b,u) — independent of h
        const float* xgp = g_xg + (size_t)(t*32 + bb)*G4H + n*8 + ub;
        float x0 = __ldcg(xgp);
        float x1 = __ldcg(xgp + Hc);
        float x2 = __ldcg(xgp + 2*Hc);
        float x3 = __ldcg(xgp + 3*Hc);

        // warp-private h slice load: warp w needs cols [128w, 128w+128) only
        {
            const __half* hsrc = g_hsh_pad + (size_t)(t*32)*Hc + w*128;
#pragma unroll
            for (int i = 0; i < 16; ++i) {
                int idx = i*32 + lane;          // 0..511
                int r = idx >> 4, cw = idx & 15;
                const uint4* gp = (const uint4*)(hsrc + (size_t)r*Hc + cw*8);
                uint4 v = __ldcg(gp);
                *(uint4*)(sH + r*L_LDH + w*128 + cw*8) = v;
            }
        }
        __syncwarp();

        // mma over this warp's K slice (A from smem via ldmatrix, W from regs)
        float acc[2][4][4];
#pragma unroll
        for (int i=0;i<2;i++)
#pragma unroll
            for (int j=0;j<4;j++)
#pragma unroll
                for (int k=0;k<4;k++) acc[i][j][k]=0.f;

#pragma unroll
        for (int kt = 0; kt < 8; ++kt) {
            const int ks = w*128 + kt*16;
            uint32_t af[2][4];
#pragma unroll
            for (int mt = 0; mt < 2; ++mt) {
                int row = mt*16 + (lane & 7) + ((lane >> 3) & 1) * 8;
                int col = ks + (lane >> 4) * 8;
                ldm_x4(af[mt], saddr(sH + row*L_LDH + col));
            }
#pragma unroll
            for (int mt = 0; mt < 2; ++mt)
#pragma unroll
                for (int nt = 0; nt < 4; ++nt)
                    mma_f16(acc[mt][nt], af[mt], bw[kt][nt]);
        }
        // dump partials: sP[w][row][col], stride 34
        float* sPw = sP + w*L_SPW;
#pragma unroll
        for (int mt = 0; mt < 2; ++mt)
#pragma unroll
            for (int nt = 0; nt < 4; ++nt) {
                int row = mt*16 + (lane >> 2);
                int col = nt*8 + (lane & 3)*2;
                *(float2*)(sPw + row*34 + col)     = make_float2(acc[mt][nt][0], acc[mt][nt][1]);
                *(float2*)(sPw + (row+8)*34 + col) = make_float2(acc[mt][nt][2], acc[mt][nt][3]);
            }
        __syncthreads();

        // reduce 8 partials + gate update; thread owns (bb, ub)
        float g0=0.f, g1=0.f, g2=0.f, g3=0.f;
#pragma unroll
        for (int ww = 0; ww < 8; ++ww) {
            const float* p = sP + ww*L_SPW + bb*34 + ub;
            g0 += p[0]; g1 += p[8]; g2 += p[16]; g3 += p[24];
        }
        float gi = sigmoidf_(g0 + x0);
        float gf = sigmoidf_(g1 + x1);
        float gg = tanhf   (g2 + x2);
        float go = sigmoidf_(g3 + x3);
        creg = gf * creg + gi * gg;
        float h = go * tanhf(creg);
        g_hsh_pad[(size_t)((t+1)*32 + bb)*Hc + n*8 + ub] = __float2half_rn(h);

        // 1-hop grid barrier (skipped on the final step; kernel-end syncs)
        __syncthreads();
        if (t + 1 < Tc) {
            if (tid == 0) {
                asm volatile("red.release.gpu.global.add.u32 [%0], %1;"
                             :: "l"(&g_sync), "r"(1u) : "memory");
                unsigned f;
                const unsigned target = 128u*(unsigned)(t+1);
                do {
                    asm volatile("ld.acquire.gpu.global.u32 %0, [%1];"
                                 : "=r"(f) : "l"(&g_sync) : "memory");
                } while (f < target);
            }
            __syncthreads();
        }
    }
}

// ---------------- FC: out = hs @ fc_w^T + fc_b ------------------------------
// CTA tile 128x128, 4 warps (2x2), warp tile 64x64, 2-stage, 3 CTAs/SM.
// Occupancy over pipeline depth: 12 warps/SM cover stage-boundary bubbles.
#define F_LD 72                        // halves per smem row (144 B)
#define F_TILE (128 * F_LD)            // halves per matrix tile
#define FC_NS 2
#define FC_SMEM (FC_NS * 2 * F_TILE * 2)   // 73728 B

__global__ void __launch_bounds__(128, 3) fc_kernel(
    const float* __restrict__ fc_b, float* __restrict__ out)
{
    extern __shared__ __half fsm[];
    const int tid = threadIdx.x, lane = tid & 31, w = tid >> 5;
    const int bm = blockIdx.x, bn = blockIdx.y;
    const int wm = (w >> 1) * 64, wn = (w & 1) * 64;

    const __half* Abase = g_hsh_pad + (size_t)Bc*Hc + (size_t)(bm*128)*Hc;
    const __half* Bbase = g_wh + (size_t)(bn*128)*Hc;

    float acc[4][8][4];
#pragma unroll
    for (int i=0;i<4;i++)
#pragma unroll
        for (int j=0;j<8;j++)
#pragma unroll
            for (int k=0;k<4;k++) acc[i][j][k]=0.f;

    auto load_stage = [&](int kt, int buf){
        __half* sA = fsm + buf * 2 * F_TILE;
        __half* sB = sA + F_TILE;
        const int k0 = kt * 64;
#pragma unroll
        for (int i = 0; i < 8; ++i) {       // A: 1024 granules / 128 thr
            int g = tid + i*128; int r = g >> 3, c = g & 7;
            cp16(saddr(sA + r*F_LD + c*8), Abase + (size_t)r*Hc + k0 + c*8);
        }
#pragma unroll
        for (int i = 0; i < 8; ++i) {       // B: 1024 granules
            int g = tid + i*128; int r = g >> 3, c = g & 7;
            cp16(saddr(sB + r*F_LD + c*8), Bbase + (size_t)r*Hc + k0 + c*8);
        }
        asm volatile("cp.async.commit_group;" ::: "memory");
    };

    load_stage(0, 0);
    load_stage(1, 1);

    for (int kt = 0; kt < 16; ++kt) {
        if (kt < 15) asm volatile("cp.async.wait_group 1;" ::: "memory");
        else         asm volatile("cp.async.wait_group 0;" ::: "memory");
        __syncthreads();

        const __half* sA = fsm + (kt & 1) * 2 * F_TILE;
        const __half* sB = sA + F_TILE;
#pragma unroll
        for (int ks = 0; ks < 64; ks += 16) {
            uint32_t af[4][4], bf[8][2];
#pragma unroll
            for (int mt = 0; mt < 4; ++mt) {
                int row = wm + mt*16 + (lane & 7) + ((lane >> 3) & 1) * 8;
                int col = ks + (lane >> 4) * 8;
                ldm_x4(af[mt], saddr(sA + row*F_LD + col));
            }
#pragma unroll
            for (int nt = 0; nt < 8; ++nt) {
                int l = lane & 15;
                int row = wn + nt*8 + (l & 7);
                int col = ks + ((l >> 3) & 1) * 8;
                ldm_x2(bf[nt], saddr(sB + row*F_LD + col));
            }
#pragma unroll
            for (int mt = 0; mt < 4; ++mt)
#pragma unroll
                for (int nt = 0; nt < 8; ++nt)
                    mma_f16(acc[mt][nt], af[mt], bf[nt]);
        }
        __syncthreads();                     // all warps done reading buffer kt&1
        if (kt + 2 < 16) load_stage(kt + 2, kt & 1);
    }

    // epilogue: + fc_b, scatter m=t*32+b -> out[(b*T+t)*V + v]
#pragma unroll
    for (int nt = 0; nt < 8; ++nt) {
        int v = bn*128 + wn + nt*8 + (lane & 3)*2;
        float bia0 = fc_b[v], bia1 = fc_b[v+1];
#pragma unroll
        for (int mt = 0; mt < 4; ++mt) {
            int m = bm*128 + wm + mt*16 + (lane >> 2);
            int b0 = m & 31, t0 = m >> 5;
            *(float2*)(out + (size_t)(b0*Tc + t0)*Vc + v) =
                make_float2(acc[mt][nt][0]+bia0, acc[mt][nt][1]+bia1);
            int m2 = m + 8;
            int b1 = m2 & 31, t1 = m2 >> 5;
            *(float2*)(out + (size_t)(b1*Tc + t1)*Vc + v) =
                make_float2(acc[mt][nt][2]+bia0, acc[mt][nt][3]+bia1);
        }
    }
}

// ---------------- launch ----------------------------------------------------
extern "C" void kernel_launch(void* const* d_in, const int* in_sizes, int n_in,
                              void* d_out, int out_size)
{
    const int*   x     = (const int*)  d_in[0];
    const float* embed = (const float*)d_in[1];
    const float* W_ih  = (const float*)d_in[2];
    const float* W_hh  = (const float*)d_in[3];
    const float* b_ih  = (const float*)d_in[4];
    const float* b_hh  = (const float*)d_in[5];
    const float* fc_w  = (const float*)d_in[6];
    const float* fc_b  = (const float*)d_in[7];
    float* out = (float*)d_out;

    cudaFuncSetAttribute(lstm_kernel, cudaFuncAttributeMaxDynamicSharedMemorySize, LSTM_SMEM);
    cudaFuncSetAttribute(fc_kernel,   cudaFuncAttributeMaxDynamicSharedMemorySize, FC_SMEM);

    init_kernel<<<32, 256>>>();
    xgprep_kernel<<<1024 + PREP_CTAS, 256>>>(x, embed, W_ih, b_ih, b_hh, fc_w);
    lstm_kernel<<<128, 256, LSTM_SMEM>>>(W_hh);
    fc_kernel<<<dim3(32, 250), 128, FC_SMEM>>>(fc_b, out);
}